// round 2
// baseline (speedup 1.0000x reference)
#include <cuda_runtime.h>
#include <cstdint>

// ChamferLoss: B=8, N=M=4096, C=3, fp32 in, scalar fp32 out.
// dist2(s,t) = |s|^2 + |t|^2 - 2 s.t
// min_t dist2 = |s|^2 - 2 * max_t (s.t - |t|^2/2)
// Inner loop per pair: 3 FFMA + 1 FMNMX.

#define BATCH     8
#define NPTS      4096
#define BN        (BATCH * NPTS)     // 32768 points per cloud total
#define THREADS   128
#define ROWS      4                  // source rows per thread (register blocking)
#define TN        (THREADS * ROWS)   // 512 sources per block
#define NM_CHUNKS 8                  // m split across blockIdx.y
#define MCHUNK    (NPTS / NM_CHUNKS) // 512 targets per block
#define TILE      128                // shared-staged targets per step
#define S2A_BLOCKS 64
#define S2A_THREADS 256

// Partial maxima: [direction][m-chunk][b*NPTS + i]. Every slot written every run.
__device__ float g_part[2][NM_CHUNKS][BN];
__device__ float g_bsum[S2A_BLOCKS];

// One direction: for each source point, max over one m-chunk of (s.t - |t|^2/2).
__global__ __launch_bounds__(THREADS)
void dir_max_kernel(const float* __restrict__ src, const float* __restrict__ tgt,
                    int dir) {
    const int b  = blockIdx.z;
    const int n0 = blockIdx.x * TN;
    const int mc = blockIdx.y;
    const int m0 = mc * MCHUNK;
    const int t  = threadIdx.x;

    __shared__ float4 sh[TILE];

    float sx[ROWS], sy[ROWS], sz[ROWS], mx[ROWS];
#pragma unroll
    for (int r = 0; r < ROWS; r++) {
        int i = n0 + t + r * THREADS;
        const float* p = src + ((size_t)b * NPTS + i) * 3;
        sx[r] = p[0]; sy[r] = p[1]; sz[r] = p[2];
        mx[r] = -3.402823466e+38f;
    }

    for (int mt = 0; mt < MCHUNK; mt += TILE) {
        __syncthreads();
        {
            int j = m0 + mt + t;  // THREADS == TILE: one target per thread
            const float* q = tgt + ((size_t)b * NPTS + j) * 3;
            float x = q[0], y = q[1], z = q[2];
            sh[t] = make_float4(x, y, z, -0.5f * (x * x + y * y + z * z));
        }
        __syncthreads();

#pragma unroll 8
        for (int j = 0; j < TILE; j++) {
            float4 q = sh[j];  // broadcast LDS.128, amortized over ROWS rows
#pragma unroll
            for (int r = 0; r < ROWS; r++) {
                float v = fmaf(sx[r], q.x, q.w);
                v = fmaf(sy[r], q.y, v);
                v = fmaf(sz[r], q.z, v);
                mx[r] = fmaxf(mx[r], v);
            }
        }
    }

#pragma unroll
    for (int r = 0; r < ROWS; r++) {
        int i = n0 + t + r * THREADS;
        g_part[dir][mc][b * NPTS + i] = mx[r];  // no atomics: dense unique slot
    }
}

// Stage 2a: per point, max over chunks -> (|p|^2 - 2*max), block-sum partials.
__global__ __launch_bounds__(S2A_THREADS)
void stage2a_kernel(const float* __restrict__ f, const float* __restrict__ f_) {
    const int gid = blockIdx.x * S2A_THREADS + threadIdx.x;
    const int nthreads = S2A_BLOCKS * S2A_THREADS;  // 16384

    float acc = 0.0f;
    for (int i = gid; i < BN; i += nthreads) {
        float m0 = g_part[0][0][i];
#pragma unroll
        for (int c = 1; c < NM_CHUNKS; c++) m0 = fmaxf(m0, g_part[0][c][i]);
        const float* p = f + (size_t)i * 3;
        acc += p[0] * p[0] + p[1] * p[1] + p[2] * p[2] - 2.0f * m0;

        float m1 = g_part[1][0][i];
#pragma unroll
        for (int c = 1; c < NM_CHUNKS; c++) m1 = fmaxf(m1, g_part[1][c][i]);
        const float* q = f_ + (size_t)i * 3;
        acc += q[0] * q[0] + q[1] * q[1] + q[2] * q[2] - 2.0f * m1;
    }

    __shared__ float red[S2A_THREADS];
    red[threadIdx.x] = acc;
    __syncthreads();
#pragma unroll
    for (int s = S2A_THREADS / 2; s > 0; s >>= 1) {
        if (threadIdx.x < s) red[threadIdx.x] += red[threadIdx.x + s];
        __syncthreads();
    }
    if (threadIdx.x == 0) g_bsum[blockIdx.x] = red[0];
}

// Stage 2b: deterministic final sum of 64 block partials.
__global__ void stage2b_kernel(float* __restrict__ out) {
    __shared__ float red[S2A_BLOCKS];
    red[threadIdx.x] = g_bsum[threadIdx.x];
    __syncthreads();
#pragma unroll
    for (int s = S2A_BLOCKS / 2; s > 0; s >>= 1) {
        if (threadIdx.x < s) red[threadIdx.x] += red[threadIdx.x + s];
        __syncthreads();
    }
    if (threadIdx.x == 0) out[0] = red[0] * (1.0f / (float)BN);
}

extern "C" void kernel_launch(void* const* d_in, const int* in_sizes, int n_in,
                              void* d_out, int out_size) {
    const float* f  = (const float*)d_in[0];
    const float* f_ = (const float*)d_in[1];
    float* out = (float*)d_out;

    dim3 grid(NPTS / TN, NM_CHUNKS, BATCH);  // (8, 8, 8) = 512 blocks
    dir_max_kernel<<<grid, THREADS>>>(f,  f_, 0);
    dir_max_kernel<<<grid, THREADS>>>(f_, f,  1);

    stage2a_kernel<<<S2A_BLOCKS, S2A_THREADS>>>(f, f_);
    stage2b_kernel<<<1, S2A_BLOCKS>>>(out);
}

// round 3
// speedup vs baseline: 1.1252x; 1.1252x over previous
#include <cuda_runtime.h>
#include <cstdint>

// ChamferLoss: B=8, N=M=4096, C=3, fp32 in, scalar fp32 out.
// dist2(s,t) = |s|^2 + |t|^2 - 2 s.t
// min_t dist2 = |s|^2 - 2 * max_t (s.t - |t|^2/2)
// Inner loop: packed fma.rn.f32x2 (2 rows per instr) -> 1.5 FFMA2 + 1 FMNMX per pair.

#define BATCH     8
#define NPTS      4096
#define BN        (BATCH * NPTS)     // 32768 points per cloud
#define THREADS   128
#define ROWS      8                  // source rows per thread
#define PAIRS     (ROWS / 2)         // packed f32x2 row-pairs
#define TN        (THREADS * ROWS)   // 1024 sources per block
#define NM_CHUNKS 32
#define MCHUNK    (NPTS / NM_CHUNKS) // 128 targets per block (== THREADS, one stage)
#define S2A_BLOCKS  64
#define S2A_THREADS 256

// Partial maxima: [dir][m-chunk][b*NPTS + i]. Every slot written every run.
__device__ float g_part[2][NM_CHUNKS][BN];
__device__ float g_bsum[S2A_BLOCKS];

typedef unsigned long long ull;

__device__ __forceinline__ ull pk2(float a, float b) {
    ull r;
    asm("mov.b64 %0, {%1, %2};" : "=l"(r) : "f"(a), "f"(b));
    return r;
}
__device__ __forceinline__ void upk2(ull v, float& lo, float& hi) {
    asm("mov.b64 {%0, %1}, %2;" : "=f"(lo), "=f"(hi) : "l"(v));
}
__device__ __forceinline__ ull fma2(ull a, ull b, ull c) {
    ull r;
    asm("fma.rn.f32x2 %0, %1, %2, %3;" : "=l"(r) : "l"(a), "l"(b), "l"(c));
    return r;
}

// Both directions in one launch: blockIdx.z in [0,16); dir = z/8, b = z%8.
__global__ __launch_bounds__(THREADS)
void dir_max_kernel(const float* __restrict__ f, const float* __restrict__ f_) {
    const int z   = blockIdx.z;
    const int dir = z >> 3;
    const int b   = z & 7;
    const float* src = dir ? f_ : f;
    const float* tgt = dir ? f  : f_;

    const int n0 = blockIdx.x * TN;
    const int mc = blockIdx.y;
    const int t  = threadIdx.x;

    // Targets staged pre-duplicated for packed math:
    // sh_xy[j] = { {x,x}, {y,y} },  sh_zw[j] = { {z,z}, {w,w} }, w = -|t|^2/2
    __shared__ ulonglong2 sh_xy[MCHUNK];
    __shared__ ulonglong2 sh_zw[MCHUNK];

    {
        int j = mc * MCHUNK + t;  // THREADS == MCHUNK
        const float* q = tgt + ((size_t)b * NPTS + j) * 3;
        float x = q[0], y = q[1], zz = q[2];
        float w = -0.5f * (x * x + y * y + zz * zz);
        sh_xy[t] = make_ulonglong2(pk2(x, x), pk2(y, y));
        sh_zw[t] = make_ulonglong2(pk2(zz, zz), pk2(w, w));
    }

    // Load 8 source rows, packed into 4 f32x2 pairs per dimension.
    ull sx2[PAIRS], sy2[PAIRS], sz2[PAIRS];
    float mx[ROWS];
#pragma unroll
    for (int p = 0; p < PAIRS; p++) {
        int i0 = n0 + t + (2 * p)     * THREADS;
        int i1 = n0 + t + (2 * p + 1) * THREADS;
        const float* p0 = src + ((size_t)b * NPTS + i0) * 3;
        const float* p1 = src + ((size_t)b * NPTS + i1) * 3;
        sx2[p] = pk2(p0[0], p1[0]);
        sy2[p] = pk2(p0[1], p1[1]);
        sz2[p] = pk2(p0[2], p1[2]);
        mx[2 * p] = -3.402823466e+38f;
        mx[2 * p + 1] = -3.402823466e+38f;
    }
    __syncthreads();

#pragma unroll 8
    for (int j = 0; j < MCHUNK; j++) {
        ulonglong2 xy = sh_xy[j];  // broadcast LDS.128
        ulonglong2 zw = sh_zw[j];
#pragma unroll
        for (int p = 0; p < PAIRS; p++) {
            ull v = fma2(sx2[p], xy.x, zw.y);   // s.x*t.x + w
            v = fma2(sy2[p], xy.y, v);
            v = fma2(sz2[p], zw.x, v);
            float v0, v1;
            upk2(v, v0, v1);                    // free: register-pair halves
            mx[2 * p]     = fmaxf(mx[2 * p],     v0);
            mx[2 * p + 1] = fmaxf(mx[2 * p + 1], v1);
        }
    }

#pragma unroll
    for (int r = 0; r < ROWS; r++) {
        int i = n0 + t + r * THREADS;
        g_part[dir][mc][b * NPTS + i] = mx[r];  // dense unique slot, no atomics
    }
}

// Stage 2a: per point, max over chunks -> (|p|^2 - 2*max), block-sum partials.
__global__ __launch_bounds__(S2A_THREADS)
void stage2a_kernel(const float* __restrict__ f, const float* __restrict__ f_) {
    const int gid = blockIdx.x * S2A_THREADS + threadIdx.x;
    const int nthreads = S2A_BLOCKS * S2A_THREADS;  // 16384

    float acc = 0.0f;
    for (int i = gid; i < BN; i += nthreads) {
        float m0 = g_part[0][0][i];
#pragma unroll
        for (int c = 1; c < NM_CHUNKS; c++) m0 = fmaxf(m0, g_part[0][c][i]);
        const float* p = f + (size_t)i * 3;
        acc += p[0] * p[0] + p[1] * p[1] + p[2] * p[2] - 2.0f * m0;

        float m1 = g_part[1][0][i];
#pragma unroll
        for (int c = 1; c < NM_CHUNKS; c++) m1 = fmaxf(m1, g_part[1][c][i]);
        const float* q = f_ + (size_t)i * 3;
        acc += q[0] * q[0] + q[1] * q[1] + q[2] * q[2] - 2.0f * m1;
    }

    __shared__ float red[S2A_THREADS];
    red[threadIdx.x] = acc;
    __syncthreads();
#pragma unroll
    for (int s = S2A_THREADS / 2; s > 0; s >>= 1) {
        if (threadIdx.x < s) red[threadIdx.x] += red[threadIdx.x + s];
        __syncthreads();
    }
    if (threadIdx.x == 0) g_bsum[blockIdx.x] = red[0];
}

// Stage 2b: deterministic final sum of 64 block partials.
__global__ void stage2b_kernel(float* __restrict__ out) {
    __shared__ float red[S2A_BLOCKS];
    red[threadIdx.x] = g_bsum[threadIdx.x];
    __syncthreads();
#pragma unroll
    for (int s = S2A_BLOCKS / 2; s > 0; s >>= 1) {
        if (threadIdx.x < s) red[threadIdx.x] += red[threadIdx.x + s];
        __syncthreads();
    }
    if (threadIdx.x == 0) out[0] = red[0] * (1.0f / (float)BN);
}

extern "C" void kernel_launch(void* const* d_in, const int* in_sizes, int n_in,
                              void* d_out, int out_size) {
    const float* f  = (const float*)d_in[0];
    const float* f_ = (const float*)d_in[1];
    float* out = (float*)d_out;

    dim3 grid(NPTS / TN, NM_CHUNKS, 2 * BATCH);  // (4, 32, 16) = 2048 blocks
    dir_max_kernel<<<grid, THREADS>>>(f, f_);

    stage2a_kernel<<<S2A_BLOCKS, S2A_THREADS>>>(f, f_);
    stage2b_kernel<<<1, S2A_BLOCKS>>>(out);
}

// round 4
// speedup vs baseline: 1.1651x; 1.0355x over previous
#include <cuda_runtime.h>
#include <cstdint>

// ChamferLoss: B=8, N=M=4096, C=3, fp32 in, scalar fp32 out.
// dist2(s,t) = |s|^2 + |t|^2 - 2 s.t ;  min_t dist2 = |s|^2 - 2 * max_t (s.t - |t|^2/2)
// Inner loop: packed fma.rn.f32x2 -> 1.5 FFMA2 + 1 FMNMX per pair.

#define BATCH     8
#define NPTS      4096
#define BN        (BATCH * NPTS)     // 32768 points per cloud
#define THREADS   128
#define ROWS      8                  // source rows per thread
#define PAIRS     (ROWS / 2)         // packed f32x2 row-pairs
#define TN        (THREADS * ROWS)   // 1024 sources per block
#define NX        (NPTS / TN)        // 4
#define NM_CHUNKS 16
#define MCHUNK    (NPTS / NM_CHUNKS) // 256 targets per block
#define TILE      128                // shared-staged targets per step (== THREADS)
#define S2_BLOCKS  64
#define S2_THREADS 256

// Partial maxima: [dir][m-chunk][b*NPTS + i]. Every slot written every run.
__device__ float g_part[2][NM_CHUNKS][BN];
__device__ float g_bsum[S2_BLOCKS];
__device__ int   g_count;  // statically 0; last block resets it for graph replay

typedef unsigned long long ull;

__device__ __forceinline__ ull pk2(float a, float b) {
    ull r;
    asm("mov.b64 %0, {%1, %2};" : "=l"(r) : "f"(a), "f"(b));
    return r;
}
__device__ __forceinline__ void upk2(ull v, float& lo, float& hi) {
    asm("mov.b64 {%0, %1}, %2;" : "=f"(lo), "=f"(hi) : "l"(v));
}
__device__ __forceinline__ ull fma2(ull a, ull b, ull c) {
    ull r;
    asm("fma.rn.f32x2 %0, %1, %2, %3;" : "=l"(r) : "l"(a), "l"(b), "l"(c));
    return r;
}

// Both directions in one launch: blockIdx.z in [0,16); dir = z/8, b = z%8.
__global__ __launch_bounds__(THREADS)
void dir_max_kernel(const float* __restrict__ f, const float* __restrict__ f_) {
    const int z   = blockIdx.z;
    const int dir = z >> 3;
    const int b   = z & 7;
    const float* src = dir ? f_ : f;
    const float* tgt = dir ? f  : f_;

    const int n0 = blockIdx.x * TN;
    const int mc = blockIdx.y;
    const int t  = threadIdx.x;

    // Targets staged pre-duplicated for packed math:
    // sh_xy[j] = { {x,x}, {y,y} },  sh_zw[j] = { {z,z}, {w,w} }, w = -|t|^2/2
    __shared__ ulonglong2 sh_xy[TILE];
    __shared__ ulonglong2 sh_zw[TILE];

    // Load 8 source rows, packed into 4 f32x2 pairs per dimension.
    ull sx2[PAIRS], sy2[PAIRS], sz2[PAIRS];
    float mx[ROWS];
#pragma unroll
    for (int p = 0; p < PAIRS; p++) {
        int i0 = n0 + t + (2 * p)     * THREADS;
        int i1 = n0 + t + (2 * p + 1) * THREADS;
        const float* p0 = src + ((size_t)b * NPTS + i0) * 3;
        const float* p1 = src + ((size_t)b * NPTS + i1) * 3;
        sx2[p] = pk2(p0[0], p1[0]);
        sy2[p] = pk2(p0[1], p1[1]);
        sz2[p] = pk2(p0[2], p1[2]);
        mx[2 * p] = -3.402823466e+38f;
        mx[2 * p + 1] = -3.402823466e+38f;
    }

    for (int mt = 0; mt < MCHUNK; mt += TILE) {
        __syncthreads();
        {
            int j = mc * MCHUNK + mt + t;  // THREADS == TILE
            const float* q = tgt + ((size_t)b * NPTS + j) * 3;
            float x = q[0], y = q[1], zz = q[2];
            float w = -0.5f * (x * x + y * y + zz * zz);
            sh_xy[t] = make_ulonglong2(pk2(x, x), pk2(y, y));
            sh_zw[t] = make_ulonglong2(pk2(zz, zz), pk2(w, w));
        }
        __syncthreads();

#pragma unroll 8
        for (int j = 0; j < TILE; j++) {
            ulonglong2 xy = sh_xy[j];  // broadcast LDS.128
            ulonglong2 zw = sh_zw[j];
#pragma unroll
            for (int p = 0; p < PAIRS; p++) {
                ull v = fma2(sx2[p], xy.x, zw.y);   // s.x*t.x + w
                v = fma2(sy2[p], xy.y, v);
                v = fma2(sz2[p], zw.x, v);
                float v0, v1;
                upk2(v, v0, v1);                    // free: register-pair halves
                mx[2 * p]     = fmaxf(mx[2 * p],     v0);
                mx[2 * p + 1] = fmaxf(mx[2 * p + 1], v1);
            }
        }
    }

#pragma unroll
    for (int r = 0; r < ROWS; r++) {
        int i = n0 + t + r * THREADS;
        g_part[dir][mc][b * NPTS + i] = mx[r];  // dense unique slot, no atomics
    }
}

// Fused stage 2: per point, max over chunks -> (|p|^2 - 2*max), block-sum;
// last block (threadfence-reduction pattern) sums the 64 partials in a fixed
// deterministic tree and writes the scalar.
__global__ __launch_bounds__(S2_THREADS)
void stage2_kernel(const float* __restrict__ f, const float* __restrict__ f_,
                   float* __restrict__ out) {
    const int tid = threadIdx.x;
    const int gid = blockIdx.x * S2_THREADS + tid;
    const int nthreads = S2_BLOCKS * S2_THREADS;  // 16384

    float acc = 0.0f;
    for (int i = gid; i < BN; i += nthreads) {
        float m0 = g_part[0][0][i];
#pragma unroll
        for (int c = 1; c < NM_CHUNKS; c++) m0 = fmaxf(m0, g_part[0][c][i]);
        const float* p = f + (size_t)i * 3;
        acc += p[0] * p[0] + p[1] * p[1] + p[2] * p[2] - 2.0f * m0;

        float m1 = g_part[1][0][i];
#pragma unroll
        for (int c = 1; c < NM_CHUNKS; c++) m1 = fmaxf(m1, g_part[1][c][i]);
        const float* q = f_ + (size_t)i * 3;
        acc += q[0] * q[0] + q[1] * q[1] + q[2] * q[2] - 2.0f * m1;
    }

    __shared__ float red[S2_THREADS];
    __shared__ bool last;
    red[tid] = acc;
    __syncthreads();
#pragma unroll
    for (int s = S2_THREADS / 2; s > 0; s >>= 1) {
        if (tid < s) red[tid] += red[tid + s];
        __syncthreads();
    }
    if (tid == 0) {
        g_bsum[blockIdx.x] = red[0];
        __threadfence();
        last = (atomicAdd(&g_count, 1) == S2_BLOCKS - 1);
    }
    __syncthreads();

    if (last) {
        __threadfence();  // acquire: make all g_bsum writes visible
        float v = (tid < S2_BLOCKS) ? g_bsum[tid] : 0.0f;
        red[tid] = v;
        __syncthreads();
#pragma unroll
        for (int s = S2_BLOCKS / 2; s > 0; s >>= 1) {
            if (tid < s) red[tid] += red[tid + s];
            __syncthreads();
        }
        if (tid == 0) {
            out[0] = red[0] * (1.0f / (float)BN);
            g_count = 0;  // reset for next graph replay
        }
    }
}

extern "C" void kernel_launch(void* const* d_in, const int* in_sizes, int n_in,
                              void* d_out, int out_size) {
    const float* f  = (const float*)d_in[0];
    const float* f_ = (const float*)d_in[1];
    float* out = (float*)d_out;

    dim3 grid(NX, NM_CHUNKS, 2 * BATCH);  // (4, 16, 16) = 1024 blocks: one wave
    dir_max_kernel<<<grid, THREADS>>>(f, f_);

    stage2_kernel<<<S2_BLOCKS, S2_THREADS>>>(f, f_, out);
}